// round 16
// baseline (speedup 1.0000x reference)
#include <cuda_runtime.h>
#include <cuda_fp16.h>
#include <math.h>
#include <stdint.h>

#define Bb 32
#define Ss 512
#define Dd 512
#define Hh 8
#define Ff 2048
#define Ll 4
#define DH 64
#define Mrows (Bb*Ss)
#define LWc ((size_t)(4*Dd*Dd+2*Dd*Ff))

typedef __half hf;

__device__ float g_x[Mrows*Dd];
__device__ float g_attn[Mrows*Dd];
__device__ float g_tmp[Mrows*Dd];
__device__ hf g_xh[Mrows*Dd];
__device__ hf g_qkvh[(size_t)Mrows*3*Dd];
__device__ hf g_ch[Mrows*Dd];
__device__ hf g_ah[Mrows*Dd];
__device__ hf g_fh[(size_t)Mrows*Ff];
__device__ hf g_wh[Ll*LWc];
__device__ hf g_pbh[(size_t)Hh*Ss*Ss];
__device__ float g_catb[Ll*3*Dd];

__device__ __forceinline__ float gelu_e(float x){return 0.5f*x*(1.0f+erff(x*0.70710678118654752f));}
__device__ __forceinline__ void cp16(uint32_t d,const void* s){
    asm volatile("cp.async.cg.shared.global [%0], [%1], 16;"::"r"(d),"l"(s));
}
#define CPC() asm volatile("cp.async.commit_group;":::"memory")
#define LDSM4(r0,r1,r2,r3,a) asm volatile("ldmatrix.sync.aligned.m8n8.x4.shared.b16 {%0,%1,%2,%3},[%4];":"=r"(r0),"=r"(r1),"=r"(r2),"=r"(r3):"r"(a))
#define LDSM4T(r0,r1,r2,r3,a) asm volatile("ldmatrix.sync.aligned.m8n8.x4.trans.shared.b16 {%0,%1,%2,%3},[%4];":"=r"(r0),"=r"(r1),"=r"(r2),"=r"(r3):"r"(a))
#define MMA(d,a,b0,b1) asm volatile( \
    "mma.sync.aligned.m16n8k16.row.col.f32.f16.f16.f32 {%0,%1,%2,%3},{%4,%5,%6,%7},{%8,%9},{%0,%1,%2,%3};" \
    :"+f"((d)[0]),"+f"((d)[1]),"+f"((d)[2]),"+f"((d)[3]) \
    :"r"((a)[0]),"r"((a)[1]),"r"((a)[2]),"r"((a)[3]),"r"(b0),"r"(b1))

__device__ __forceinline__ uint32_t pack2(float a,float b){
    __half2 H=__halves2half2(__float2half_rn(a),__float2half_rn(b));
    return *(uint32_t*)&H;
}

// ============== GEMM: pure fp16, BK=64, 3-stage =================================
#define STB2 32768
#define GSMEM (3*STB2)
__device__ __forceinline__ void load_stage(uint32_t st,int tid,
    const hf* Ah,const hf* Bh,int m0,int n0,int k0,int K){
    #pragma unroll
    for(int i=0;i<8;i++){
        int id=i*256+tid;
        int reg=id>>10, rid=id&1023, row=rid>>3, c=rid&7;
        const hf* src=reg? Bh+(size_t)(n0+row)*K+k0+c*8 : Ah+(size_t)(m0+row)*K+k0+c*8;
        cp16(st+reg*16384+row*128+((c^(row&7))*16),src);
    }
    CPC();
}

// OUT: 0=fp32, 2=fp16
template<int ACT, bool RES, int OUT, int KT>
__global__ void __launch_bounds__(256,2)
gemm_mma(const hf* __restrict__ Ah,const hf* __restrict__ Bh,
         const float* __restrict__ bias,const float* __restrict__ res,
         float* __restrict__ C,hf* __restrict__ Ch,
         int N){
    extern __shared__ char sm[];
    uint32_t sb=(uint32_t)__cvta_generic_to_shared(sm);
    const int tid=threadIdx.x, wid=tid>>5, lane=tid&31;
    const int n0=blockIdx.x*128, m0=blockIdx.y*128;
    const int wm=(wid>>2)*64, wn=(wid&3)*32;
    constexpr int chunks=KT>>6;
    float acc[4][4][4];
    #pragma unroll
    for(int i=0;i<4;i++)
        #pragma unroll
        for(int j=0;j<4;j++){acc[i][j][0]=0;acc[i][j][1]=0;acc[i][j][2]=0;acc[i][j][3]=0;}
    load_stage(sb,tid,Ah,Bh,m0,n0,0,KT);
    load_stage(sb+STB2,tid,Ah,Bh,m0,n0,64,KT);
    const int arow=lane&15, ah8=lane>>4;
    int s2=2;
    for(int c=0;c<chunks;c++){
        uint32_t st=sb+(c%3)*STB2;
        if(c<chunks-1) asm volatile("cp.async.wait_group 1;":::"memory");
        else           asm volatile("cp.async.wait_group 0;":::"memory");
        __syncthreads();
        if(c+2<chunks){
            load_stage(sb+s2*STB2,tid,Ah,Bh,m0,n0,(c+2)*64,KT);
            s2++; if(s2==3)s2=0;
        }
        #pragma unroll
        for(int s=0;s<4;s++){
            uint32_t bhf[2][4];
            #pragma unroll
            for(int nq=0;nq<2;nq++){
                int row=wn+nq*16+arow;
                uint32_t ad=st+16384+row*128+(((s*2+ah8)^(row&7))*16);
                LDSM4(bhf[nq][0],bhf[nq][1],bhf[nq][2],bhf[nq][3],ad);
            }
            #pragma unroll
            for(int mi=0;mi<4;mi++){
                uint32_t ahf[4];
                int row=wm+mi*16+arow;
                uint32_t ad=st+row*128+(((s*2+ah8)^(row&7))*16);
                LDSM4(ahf[0],ahf[1],ahf[2],ahf[3],ad);
                #pragma unroll
                for(int nq=0;nq<2;nq++)
                    #pragma unroll
                    for(int p=0;p<2;p++)
                        MMA(acc[mi][nq*2+p],ahf,bhf[nq][p],bhf[nq][p+2]);
            }
        }
    }
    const int r4=lane>>2, c2=(lane&3)*2;
    #pragma unroll
    for(int mi=0;mi<4;mi++)
        #pragma unroll
        for(int nt=0;nt<4;nt++){
            int col=n0+wn+nt*8+c2;
            float2 bv=*(const float2*)&bias[col];
            #pragma unroll
            for(int hr=0;hr<2;hr++){
                int row=m0+wm+mi*16+r4+hr*8;
                float2 o;
                o.x=acc[mi][nt][hr*2+0]+bv.x;
                o.y=acc[mi][nt][hr*2+1]+bv.y;
                if(RES){float2 rv=*(const float2*)&res[(size_t)row*N+col]; o.x+=rv.x;o.y+=rv.y;}
                if(ACT==1){o.x=gelu_e(o.x);o.y=gelu_e(o.y);}
                if(OUT==0) *(float2*)&C[(size_t)row*N+col]=o;
                else       *(uint32_t*)&Ch[(size_t)row*N+col]=pack2(o.x,o.y);
            }
        }
}

// ===== flash attention: fp16 operands, 3-stage KV ring, rational scale ==========
#define FLSM (16384 + 3*16384)
__global__ void __launch_bounds__(256,2)
flash_k(const hf* __restrict__ qkvh,
        const hf* __restrict__ pbh,const long long* __restrict__ ts,
        hf* __restrict__ Ch){
    extern __shared__ char sm[];
    uint32_t sb=(uint32_t)__cvta_generic_to_shared(sm);
    const int tid=threadIdx.x, wid=tid>>5, lane=tid&31;
    const int bh=blockIdx.y, b=bh>>3, h=bh&7;
    const int q0=blockIdx.x*128;
    const int wm=wid*16;
    const int arow=lane&15, ah8=lane>>4, r4=lane>>2, j2=(lane&3)*2;

    #pragma unroll
    for(int i=0;i<4;i++){
        int id=i*256+tid;
        int row=id>>3, c=id&7;
        const hf* src=qkvh+(size_t)(b*Ss+q0+row)*1536+h*DH+c*8;
        cp16(sb+row*128+((c^(row&7))*16),src);
    }
    CPC();

    auto loadkv=[&](int st,int k0){
        #pragma unroll
        for(int i=0;i<4;i++){
            int id=i*256+tid;
            int part=id>>9, rid=id&511, row=rid>>3, c=rid&7;
            int colb=part? (2*Dd+h*DH) : (Dd+h*DH);
            const hf* src=qkvh+(size_t)(b*Ss+k0+row)*1536+colb+c*8;
            cp16(sb+16384+st*16384+part*8192+row*128+((c^(row&7))*16),src);
        }
        CPC();
    };
    loadkv(0,0); loadkv(1,64);

    float m0_=-1e30f, m1_=-1e30f, l0_=0.0f, l1_=0.0f;
    float oacc[8][4];
    #pragma unroll
    for(int i=0;i<8;i++){oacc[i][0]=0;oacc[i][1]=0;oacc[i][2]=0;oacc[i][3]=0;}
    const long long tq0=ts[b*Ss+q0+wm+r4], tq1=ts[b*Ss+q0+wm+r4+8];
    const int qi0=q0+wm+r4, qi1=qi0+8;
    const hf* pb0p=pbh+(size_t)(h*Ss+qi0)*Ss;
    const hf* pb1p=pbh+(size_t)(h*Ss+qi1)*Ss;
    int s2=2;

    for(int t=0;t<8;t++){
        uint32_t stv=sb+16384+(t%3)*16384;
        if(t<7) asm volatile("cp.async.wait_group 1;":::"memory");
        else    asm volatile("cp.async.wait_group 0;":::"memory");
        __syncthreads();
        if(t+2<8){
            loadkv(s2,(t+2)*64);
            s2++; if(s2==3)s2=0;
        }

        float sacc[8][4];
        #pragma unroll
        for(int i=0;i<8;i++){sacc[i][0]=0;sacc[i][1]=0;sacc[i][2]=0;sacc[i][3]=0;}
        #pragma unroll
        for(int kt=0;kt<4;kt++){
            uint32_t qh_[4];
            {
                int row=wm+arow;
                uint32_t ad=sb+row*128+(((kt*2+ah8)^(row&7))*16);
                LDSM4(qh_[0],qh_[1],qh_[2],qh_[3],ad);
            }
            #pragma unroll
            for(int nq=0;nq<4;nq++){
                int row=nq*16+arow;
                uint32_t ad=stv+row*128+(((kt*2+ah8)^(row&7))*16);
                uint32_t kh_[4];
                LDSM4(kh_[0],kh_[1],kh_[2],kh_[3],ad);
                #pragma unroll
                for(int p=0;p<2;p++)
                    MMA(sacc[nq*2+p],qh_,kh_[p],kh_[p+2]);
            }
        }
        int k0=t*64;
        #pragma unroll
        for(int nt=0;nt<8;nt++){
            int kc=k0+nt*8+j2;
            long long tk0=ts[b*Ss+kc], tk1=ts[b*Ss+kc+1];
            float la0=fmaxf((float)(tq0-tk0)*(1.0f/60000.0f),0.0f);
            float lb0=fmaxf((float)(tq0-tk1)*(1.0f/60000.0f),0.0f);
            float la1=fmaxf((float)(tq1-tk0)*(1.0f/60000.0f),0.0f);
            float lb1=fmaxf((float)(tq1-tk1)*(1.0f/60000.0f),0.0f);
            float2 pb0=__half22float2(*(const __half2*)&pb0p[kc]);
            float2 pb1=__half22float2(*(const __half2*)&pb1p[kc]);
            sacc[nt][0]=sacc[nt][0]*__fdividef(la0+1.0f,9.0f*la0+8.0f)+pb0.x;
            sacc[nt][1]=sacc[nt][1]*__fdividef(lb0+1.0f,9.0f*lb0+8.0f)+pb0.y;
            sacc[nt][2]=sacc[nt][2]*__fdividef(la1+1.0f,9.0f*la1+8.0f)+pb1.x;
            sacc[nt][3]=sacc[nt][3]*__fdividef(lb1+1.0f,9.0f*lb1+8.0f)+pb1.y;
        }
        float tm0=-1e30f, tm1=-1e30f;
        #pragma unroll
        for(int nt=0;nt<8;nt++){
            tm0=fmaxf(tm0,fmaxf(sacc[nt][0],sacc[nt][1]));
            tm1=fmaxf(tm1,fmaxf(sacc[nt][2],sacc[nt][3]));
        }
        tm0=fmaxf(tm0,__shfl_xor_sync(0xffffffffu,tm0,1));
        tm0=fmaxf(tm0,__shfl_xor_sync(0xffffffffu,tm0,2));
        tm1=fmaxf(tm1,__shfl_xor_sync(0xffffffffu,tm1,1));
        tm1=fmaxf(tm1,__shfl_xor_sync(0xffffffffu,tm1,2));
        float mn0=fmaxf(m0_,tm0), mn1=fmaxf(m1_,tm1);
        float al0=__expf(m0_-mn0), al1=__expf(m1_-mn1);
        m0_=mn0; m1_=mn1;
        float s0=0.0f, s1=0.0f;
        #pragma unroll
        for(int nt=0;nt<8;nt++){
            sacc[nt][0]=__expf(sacc[nt][0]-mn0); s0+=sacc[nt][0];
            sacc[nt][1]=__expf(sacc[nt][1]-mn0); s0+=sacc[nt][1];
            sacc[nt][2]=__expf(sacc[nt][2]-mn1); s1+=sacc[nt][2];
            sacc[nt][3]=__expf(sacc[nt][3]-mn1); s1+=sacc[nt][3];
        }
        s0+=__shfl_xor_sync(0xffffffffu,s0,1); s0+=__shfl_xor_sync(0xffffffffu,s0,2);
        s1+=__shfl_xor_sync(0xffffffffu,s1,1); s1+=__shfl_xor_sync(0xffffffffu,s1,2);
        l0_=l0_*al0+s0; l1_=l1_*al1+s1;
        #pragma unroll
        for(int nt=0;nt<8;nt++){
            oacc[nt][0]*=al0; oacc[nt][1]*=al0;
            oacc[nt][2]*=al1; oacc[nt][3]*=al1;
        }
        uint32_t ph_[4][4];
        #pragma unroll
        for(int kt=0;kt<4;kt++){
            ph_[kt][0]=pack2(sacc[2*kt][0],  sacc[2*kt][1]);
            ph_[kt][1]=pack2(sacc[2*kt][2],  sacc[2*kt][3]);
            ph_[kt][2]=pack2(sacc[2*kt+1][0],sacc[2*kt+1][1]);
            ph_[kt][3]=pack2(sacc[2*kt+1][2],sacc[2*kt+1][3]);
        }
        #pragma unroll
        for(int kt=0;kt<4;kt++){
            #pragma unroll
            for(int dg=0;dg<4;dg++){
                int row=kt*16+((lane>>3)&1)*8+(lane&7);
                int ch_=dg*2+(lane>>4);
                uint32_t ad=stv+8192+row*128+((ch_^(row&7))*16);
                uint32_t vh_[4];
                LDSM4T(vh_[0],vh_[1],vh_[2],vh_[3],ad);
                #pragma unroll
                for(int p=0;p<2;p++)
                    MMA(oacc[dg*2+p],ph_[kt],vh_[p*2],vh_[p*2+1]);
            }
        }
    }
    float inv0=__fdividef(1.0f,l0_), inv1=__fdividef(1.0f,l1_);
    #pragma unroll
    for(int nt=0;nt<8;nt++){
        int dh=nt*8+j2;
        *(uint32_t*)&Ch[((size_t)(b*Ss+qi0))*Dd+h*DH+dh]=pack2(oacc[nt][0]*inv0,oacc[nt][1]*inv0);
        *(uint32_t*)&Ch[((size_t)(b*Ss+qi1))*Dd+h*DH+dh]=pack2(oacc[nt][2]*inv1,oacc[nt][3]*inv1);
    }
}

// ================= LayerNorm: fp32 in -> fp32 out + fp16 out ====================
__global__ void ln_k(const float* __restrict__ in,const float* __restrict__ g,
                     const float* __restrict__ bt,float* __restrict__ out,
                     hf* __restrict__ oh){
    const size_t row=blockIdx.x;
    const int tid=threadIdx.x, lane=tid&31, wid=tid>>5;
    __shared__ float red[4];
    float4 v=*(const float4*)&in[row*Dd+tid*4];
    float s=v.x+v.y+v.z+v.w;
    #pragma unroll
    for(int o=16;o;o>>=1)s+=__shfl_xor_sync(0xffffffffu,s,o);
    if(lane==0)red[wid]=s;
    __syncthreads();
    float mu=(red[0]+red[1]+red[2]+red[3])*(1.0f/512.0f);
    __syncthreads();
    float dx=v.x-mu,dy=v.y-mu,dz=v.z-mu,dw=v.w-mu;
    float s2=dx*dx+dy*dy+dz*dz+dw*dw;
    #pragma unroll
    for(int o=16;o;o>>=1)s2+=__shfl_xor_sync(0xffffffffu,s2,o);
    if(lane==0)red[wid]=s2;
    __syncthreads();
    float var=(red[0]+red[1]+red[2]+red[3])*(1.0f/512.0f);
    float inv=rsqrtf(var+1e-12f);
    float4 gv=*(const float4*)&g[tid*4];
    float4 bv=*(const float4*)&bt[tid*4];
    float4 o;
    o.x=dx*inv*gv.x+bv.x; o.y=dy*inv*gv.y+bv.y;
    o.z=dz*inv*gv.z+bv.z; o.w=dw*inv*gv.w+bv.w;
    *(float4*)&out[row*Dd+tid*4]=o;
    ((uint32_t*)(oh+row*Dd+tid*4))[0]=pack2(o.x,o.y);
    ((uint32_t*)(oh+row*Dd+tid*4))[1]=pack2(o.z,o.w);
}

__global__ void split_k(const float* __restrict__ s,hf* __restrict__ hi,int n4){
    int i=blockIdx.x*256+threadIdx.x;
    if(i>=n4)return;
    float4 v=((const float4*)s)[i];
    ((uint32_t*)hi)[i*2+0]=pack2(v.x,v.y);
    ((uint32_t*)hi)[i*2+1]=pack2(v.z,v.w);
}

__global__ void wprep_k(const float* __restrict__ Wq,const float* __restrict__ Wk,
                        const float* __restrict__ Wv,const float* __restrict__ Wo,
                        const float* __restrict__ Wi,const float* __restrict__ Wf,
                        hf* __restrict__ wh){
    __shared__ float t[32][33];
    int tile=blockIdx.x;
    int l=tile/3072, r=tile%3072;
    const float* src; size_t off; int K,N;
    if(r<1024){
        int m=r>>8; r&=255;
        src=(m==0?Wq:m==1?Wk:m==2?Wv:Wo)+(size_t)l*Dd*Dd;
        off=(size_t)m*Dd*Dd; K=Dd; N=Dd;
    }else if(r<2048){
        r-=1024; src=Wi+(size_t)l*Dd*Ff; off=4*Dd*Dd; K=Dd; N=Ff;
    }else{
        r-=2048; src=Wf+(size_t)l*Ff*Dd; off=4*Dd*Dd+(size_t)Dd*Ff; K=Ff; N=Dd;
    }
    hf* dh=wh+(size_t)l*LWc+off;
    int ntk=K>>5;
    int n0=(r/ntk)*32, k0=(r%ntk)*32;
    int x=threadIdx.x, y0=threadIdx.y;
    for(int j=y0;j<32;j+=8) t[j][x]=src[(size_t)(k0+j)*N+n0+x];
    __syncthreads();
    for(int j=y0;j<32;j+=8)
        dh[(size_t)(n0+j)*K+k0+x]=__float2half_rn(t[x][j]);
}

__global__ void catb_k(const float* bq,const float* bk,const float* bv,float* o,
                       const float* pb,hf* pbh){
    int i=blockIdx.x*256+threadIdx.x;
    if(i<Ll*3*Dd){
        int l=i/(3*Dd), r=i%(3*Dd);
        o[i]= r<Dd ? bq[l*Dd+r] : (r<2*Dd ? bk[l*Dd+r-Dd] : bv[l*Dd+r-2*Dd]);
    }
    int n4=(int)((size_t)Hh*Ss*Ss/4);
    for(int j=i;j<n4;j+=gridDim.x*256){
        float4 v=((const float4*)pb)[j];
        ((uint32_t*)pbh)[j*2+0]=pack2(v.x,v.y);
        ((uint32_t*)pbh)[j*2+1]=pack2(v.z,v.w);
    }
}

extern "C" void kernel_launch(void* const* d_in, const int* in_sizes, int n_in,
                              void* d_out, int out_size){
    const float* hidden=(const float*)d_in[0];
    const float* pbias=(const float*)d_in[1];
    const long long* ts=(const long long*)d_in[2];
    const float* Wq=(const float*)d_in[3];  const float* bq=(const float*)d_in[4];
    const float* Wk=(const float*)d_in[5];  const float* bk=(const float*)d_in[6];
    const float* Wv=(const float*)d_in[7];  const float* bv=(const float*)d_in[8];
    const float* Wo=(const float*)d_in[9];  const float* bo=(const float*)d_in[10];
    const float* l1g=(const float*)d_in[11];const float* l1b=(const float*)d_in[12];
    const float* Wi=(const float*)d_in[13]; const float* bi=(const float*)d_in[14];
    const float* Wf=(const float*)d_in[15]; const float* bfp=(const float*)d_in[16];
    const float* l2g=(const float*)d_in[17];const float* l2b=(const float*)d_in[18];

    float *px,*pattn,*ptmp,*pcatb;
    cudaGetSymbolAddress((void**)&px,g_x);     cudaGetSymbolAddress((void**)&pattn,g_attn);
    cudaGetSymbolAddress((void**)&ptmp,g_tmp); cudaGetSymbolAddress((void**)&pcatb,g_catb);
    hf *xh,*qkh,*ch,*ah,*fh,*wh,*pbh;
    cudaGetSymbolAddress((void**)&xh,g_xh);
    cudaGetSymbolAddress((void**)&qkh,g_qkvh);
    cudaGetSymbolAddress((void**)&ch,g_ch);
    cudaGetSymbolAddress((void**)&ah,g_ah);
    cudaGetSymbolAddress((void**)&fh,g_fh);
    cudaGetSymbolAddress((void**)&wh,g_wh);
    cudaGetSymbolAddress((void**)&pbh,g_pbh);

    cudaFuncSetAttribute(gemm_mma<0,false,2,512>, cudaFuncAttributeMaxDynamicSharedMemorySize,GSMEM);
    cudaFuncSetAttribute(gemm_mma<0,true,0,512>,  cudaFuncAttributeMaxDynamicSharedMemorySize,GSMEM);
    cudaFuncSetAttribute(gemm_mma<1,false,2,512>, cudaFuncAttributeMaxDynamicSharedMemorySize,GSMEM);
    cudaFuncSetAttribute(gemm_mma<0,true,0,2048>, cudaFuncAttributeMaxDynamicSharedMemorySize,GSMEM);
    cudaFuncSetAttribute(flash_k,cudaFuncAttributeMaxDynamicSharedMemorySize,FLSM);

    wprep_k<<<Ll*3072,dim3(32,8)>>>(Wq,Wk,Wv,Wo,Wi,Wf,wh);
    catb_k<<<512,256>>>(bq,bk,bv,pcatb,pbias,pbh);
    const int nD4=Mrows*Dd/4;
    split_k<<<(nD4+255)/256,256>>>(hidden,xh,nD4);

    const dim3 gDD(Dd/128,Mrows/128), gQKV(3*Dd/128,Mrows/128), gDF(Ff/128,Mrows/128);
    const float* X=hidden;
    for(int l=0;l<Ll;l++){
        hf* bh_=wh+(size_t)l*LWc;
        hf* wih=bh_+4*Dd*Dd;
        hf* wfh=wih+(size_t)Dd*Ff;
        float* xout=(l==Ll-1)? (float*)d_out : px;

        gemm_mma<0,false,2,512><<<gQKV,256,GSMEM>>>(xh,bh_,pcatb+l*3*Dd,nullptr,nullptr,qkh,3*Dd);
        flash_k<<<dim3(4,Bb*Hh),256,FLSM>>>(qkh,pbh,ts,ch);

        gemm_mma<0,true,0,512><<<gDD,256,GSMEM>>>(ch,bh_+3*Dd*Dd,bo+l*Dd,X,ptmp,nullptr,Dd);
        ln_k<<<Mrows,128>>>(ptmp,l1g+l*Dd,l1b+l*Dd,pattn,ah);

        gemm_mma<1,false,2,512><<<gDF,256,GSMEM>>>(ah,wih,bi+l*Ff,nullptr,nullptr,fh,Ff);
        gemm_mma<0,true,0,2048><<<gDD,256,GSMEM>>>(fh,wfh,bfp+l*Dd,pattn,ptmp,nullptr,Dd);
        ln_k<<<Mrows,128>>>(ptmp,l2g+l*Dd,l2b+l*Dd,xout,xh);
        X=xout;
    }
}

// round 17
// speedup vs baseline: 1.1320x; 1.1320x over previous
#include <cuda_runtime.h>
#include <cuda_fp16.h>
#include <math.h>
#include <stdint.h>

#define Bb 32
#define Ss 512
#define Dd 512
#define Hh 8
#define Ff 2048
#define Ll 4
#define DH 64
#define Mrows (Bb*Ss)
#define LWc ((size_t)(4*Dd*Dd+2*Dd*Ff))

typedef __half hf;

__device__ float g_x[Mrows*Dd];
__device__ float g_attn[Mrows*Dd];
__device__ float g_tmp[Mrows*Dd];
__device__ hf g_xh[Mrows*Dd];
__device__ hf g_qkvh[(size_t)Mrows*3*Dd];
__device__ hf g_ch[Mrows*Dd];
__device__ hf g_ah[Mrows*Dd];
__device__ hf g_fh[(size_t)Mrows*Ff];
__device__ hf g_wh[Ll*LWc];
__device__ hf g_pbh[(size_t)Hh*Ss*Ss];
__device__ float g_catb[Ll*3*Dd];

__device__ __forceinline__ float gelu_e(float x){return 0.5f*x*(1.0f+erff(x*0.70710678118654752f));}
__device__ __forceinline__ void cp16(uint32_t d,const void* s){
    asm volatile("cp.async.cg.shared.global [%0], [%1], 16;"::"r"(d),"l"(s));
}
#define CPC() asm volatile("cp.async.commit_group;":::"memory")
#define LDSM4(r0,r1,r2,r3,a) asm volatile("ldmatrix.sync.aligned.m8n8.x4.shared.b16 {%0,%1,%2,%3},[%4];":"=r"(r0),"=r"(r1),"=r"(r2),"=r"(r3):"r"(a))
#define LDSM4T(r0,r1,r2,r3,a) asm volatile("ldmatrix.sync.aligned.m8n8.x4.trans.shared.b16 {%0,%1,%2,%3},[%4];":"=r"(r0),"=r"(r1),"=r"(r2),"=r"(r3):"r"(a))
#define MMA(d,a,b0,b1) asm volatile( \
    "mma.sync.aligned.m16n8k16.row.col.f32.f16.f16.f32 {%0,%1,%2,%3},{%4,%5,%6,%7},{%8,%9},{%0,%1,%2,%3};" \
    :"+f"((d)[0]),"+f"((d)[1]),"+f"((d)[2]),"+f"((d)[3]) \
    :"r"((a)[0]),"r"((a)[1]),"r"((a)[2]),"r"((a)[3]),"r"(b0),"r"(b1))

__device__ __forceinline__ uint32_t pack2(float a,float b){
    __half2 H=__halves2half2(__float2half_rn(a),__float2half_rn(b));
    return *(uint32_t*)&H;
}

// ============== GEMM: pure fp16, BK=64, 3-stage =================================
#define STB2 32768
#define GSMEM (3*STB2)
__device__ __forceinline__ void load_stage(uint32_t st,int tid,
    const hf* Ah,const hf* Bh,int m0,int n0,int k0,int K){
    #pragma unroll
    for(int i=0;i<8;i++){
        int id=i*256+tid;
        int reg=id>>10, rid=id&1023, row=rid>>3, c=rid&7;
        const hf* src=reg? Bh+(size_t)(n0+row)*K+k0+c*8 : Ah+(size_t)(m0+row)*K+k0+c*8;
        cp16(st+reg*16384+row*128+((c^(row&7))*16),src);
    }
    CPC();
}

// OUT: 0=fp32, 2=fp16
template<int ACT, bool RES, int OUT, int KT>
__global__ void __launch_bounds__(256,2)
gemm_mma(const hf* __restrict__ Ah,const hf* __restrict__ Bh,
         const float* __restrict__ bias,const float* __restrict__ res,
         float* __restrict__ C,hf* __restrict__ Ch,
         int N){
    extern __shared__ char sm[];
    uint32_t sb=(uint32_t)__cvta_generic_to_shared(sm);
    const int tid=threadIdx.x, wid=tid>>5, lane=tid&31;
    const int n0=blockIdx.x*128, m0=blockIdx.y*128;
    const int wm=(wid>>2)*64, wn=(wid&3)*32;
    constexpr int chunks=KT>>6;
    float acc[4][4][4];
    #pragma unroll
    for(int i=0;i<4;i++)
        #pragma unroll
        for(int j=0;j<4;j++){acc[i][j][0]=0;acc[i][j][1]=0;acc[i][j][2]=0;acc[i][j][3]=0;}
    load_stage(sb,tid,Ah,Bh,m0,n0,0,KT);
    load_stage(sb+STB2,tid,Ah,Bh,m0,n0,64,KT);
    const int arow=lane&15, ah8=lane>>4;
    int s2=2;
    for(int c=0;c<chunks;c++){
        uint32_t st=sb+(c%3)*STB2;
        if(c<chunks-1) asm volatile("cp.async.wait_group 1;":::"memory");
        else           asm volatile("cp.async.wait_group 0;":::"memory");
        __syncthreads();
        if(c+2<chunks){
            load_stage(sb+s2*STB2,tid,Ah,Bh,m0,n0,(c+2)*64,KT);
            s2++; if(s2==3)s2=0;
        }
        #pragma unroll
        for(int s=0;s<4;s++){
            uint32_t bhf[2][4];
            #pragma unroll
            for(int nq=0;nq<2;nq++){
                int row=wn+nq*16+arow;
                uint32_t ad=st+16384+row*128+(((s*2+ah8)^(row&7))*16);
                LDSM4(bhf[nq][0],bhf[nq][1],bhf[nq][2],bhf[nq][3],ad);
            }
            #pragma unroll
            for(int mi=0;mi<4;mi++){
                uint32_t ahf[4];
                int row=wm+mi*16+arow;
                uint32_t ad=st+row*128+(((s*2+ah8)^(row&7))*16);
                LDSM4(ahf[0],ahf[1],ahf[2],ahf[3],ad);
                #pragma unroll
                for(int nq=0;nq<2;nq++)
                    #pragma unroll
                    for(int p=0;p<2;p++)
                        MMA(acc[mi][nq*2+p],ahf,bhf[nq][p],bhf[nq][p+2]);
            }
        }
    }
    const int r4=lane>>2, c2=(lane&3)*2;
    #pragma unroll
    for(int mi=0;mi<4;mi++)
        #pragma unroll
        for(int nt=0;nt<4;nt++){
            int col=n0+wn+nt*8+c2;
            float2 bv=*(const float2*)&bias[col];
            #pragma unroll
            for(int hr=0;hr<2;hr++){
                int row=m0+wm+mi*16+r4+hr*8;
                float2 o;
                o.x=acc[mi][nt][hr*2+0]+bv.x;
                o.y=acc[mi][nt][hr*2+1]+bv.y;
                if(RES){float2 rv=*(const float2*)&res[(size_t)row*N+col]; o.x+=rv.x;o.y+=rv.y;}
                if(ACT==1){o.x=gelu_e(o.x);o.y=gelu_e(o.y);}
                if(OUT==0) *(float2*)&C[(size_t)row*N+col]=o;
                else       *(uint32_t*)&Ch[(size_t)row*N+col]=pack2(o.x,o.y);
            }
        }
}

// ===== flash attention: fp16 operands, 3-stage KV ring, smem float timestamps ===
#define FTS_OFF (16384 + 3*16384)
#define FLSM (FTS_OFF + 2048)
__global__ void __launch_bounds__(256,2)
flash_k(const hf* __restrict__ qkvh,
        const hf* __restrict__ pbh,const long long* __restrict__ ts,
        hf* __restrict__ Ch){
    extern __shared__ char sm[];
    uint32_t sb=(uint32_t)__cvta_generic_to_shared(sm);
    float* fts=(float*)(sm+FTS_OFF);
    const int tid=threadIdx.x, wid=tid>>5, lane=tid&31;
    const int bh=blockIdx.y, b=bh>>3, h=bh&7;
    const int q0=blockIdx.x*128;
    const int wm=wid*16;
    const int arow=lane&15, ah8=lane>>4, r4=lane>>2, j2=(lane&3)*2;

    #pragma unroll
    for(int i=0;i<4;i++){
        int id=i*256+tid;
        int row=id>>3, c=id&7;
        const hf* src=qkvh+(size_t)(b*Ss+q0+row)*1536+h*DH+c*8;
        cp16(sb+row*128+((c^(row&7))*16),src);
    }
    CPC();

    auto loadkv=[&](int st,int k0){
        #pragma unroll
        for(int i=0;i<4;i++){
            int id=i*256+tid;
            int part=id>>9, rid=id&511, row=rid>>3, c=rid&7;
            int colb=part? (2*Dd+h*DH) : (Dd+h*DH);
            const hf* src=qkvh+(size_t)(b*Ss+k0+row)*1536+colb+c*8;
            cp16(sb+16384+st*16384+part*8192+row*128+((c^(row&7))*16),src);
        }
        CPC();
    };
    loadkv(0,0); loadkv(1,64);

    // batch timestamps -> smem as pre-divided floats (exact cast: ts < 2^24)
    fts[tid]      =(float)ts[b*Ss+tid]      *(1.0f/60000.0f);
    fts[tid+256]  =(float)ts[b*Ss+tid+256]  *(1.0f/60000.0f);

    float m0_=-1e30f, m1_=-1e30f, l0_=0.0f, l1_=0.0f;
    float oacc[8][4];
    #pragma unroll
    for(int i=0;i<8;i++){oacc[i][0]=0;oacc[i][1]=0;oacc[i][2]=0;oacc[i][3]=0;}
    const int qi0=q0+wm+r4, qi1=qi0+8;
    const float tq0f=(float)ts[b*Ss+qi0]*(1.0f/60000.0f);
    const float tq1f=(float)ts[b*Ss+qi1]*(1.0f/60000.0f);
    const hf* pb0p=pbh+(size_t)(h*Ss+qi0)*Ss;
    const hf* pb1p=pbh+(size_t)(h*Ss+qi1)*Ss;
    int s2=2;

    for(int t=0;t<8;t++){
        uint32_t stv=sb+16384+(t%3)*16384;
        if(t<7) asm volatile("cp.async.wait_group 1;":::"memory");
        else    asm volatile("cp.async.wait_group 0;":::"memory");
        __syncthreads();
        if(t+2<8){
            loadkv(s2,(t+2)*64);
            s2++; if(s2==3)s2=0;
        }

        float sacc[8][4];
        #pragma unroll
        for(int i=0;i<8;i++){sacc[i][0]=0;sacc[i][1]=0;sacc[i][2]=0;sacc[i][3]=0;}
        #pragma unroll
        for(int kt=0;kt<4;kt++){
            uint32_t qh_[4];
            {
                int row=wm+arow;
                uint32_t ad=sb+row*128+(((kt*2+ah8)^(row&7))*16);
                LDSM4(qh_[0],qh_[1],qh_[2],qh_[3],ad);
            }
            #pragma unroll
            for(int nq=0;nq<4;nq++){
                int row=nq*16+arow;
                uint32_t ad=stv+row*128+(((kt*2+ah8)^(row&7))*16);
                uint32_t kh_[4];
                LDSM4(kh_[0],kh_[1],kh_[2],kh_[3],ad);
                #pragma unroll
                for(int p=0;p<2;p++)
                    MMA(sacc[nq*2+p],qh_,kh_[p],kh_[p+2]);
            }
        }
        int k0=t*64;
        #pragma unroll
        for(int nt=0;nt<8;nt++){
            int kc=k0+nt*8+j2;
            float fk0=fts[kc], fk1=fts[kc+1];
            float la0=fmaxf(tq0f-fk0,0.0f);
            float lb0=fmaxf(tq0f-fk1,0.0f);
            float la1=fmaxf(tq1f-fk0,0.0f);
            float lb1=fmaxf(tq1f-fk1,0.0f);
            float2 pb0=__half22float2(*(const __half2*)&pb0p[kc]);
            float2 pb1=__half22float2(*(const __half2*)&pb1p[kc]);
            sacc[nt][0]=sacc[nt][0]*__fdividef(la0+1.0f,9.0f*la0+8.0f)+pb0.x;
            sacc[nt][1]=sacc[nt][1]*__fdividef(lb0+1.0f,9.0f*lb0+8.0f)+pb0.y;
            sacc[nt][2]=sacc[nt][2]*__fdividef(la1+1.0f,9.0f*la1+8.0f)+pb1.x;
            sacc[nt][3]=sacc[nt][3]*__fdividef(lb1+1.0f,9.0f*lb1+8.0f)+pb1.y;
        }
        float tm0=-1e30f, tm1=-1e30f;
        #pragma unroll
        for(int nt=0;nt<8;nt++){
            tm0=fmaxf(tm0,fmaxf(sacc[nt][0],sacc[nt][1]));
            tm1=fmaxf(tm1,fmaxf(sacc[nt][2],sacc[nt][3]));
        }
        tm0=fmaxf(tm0,__shfl_xor_sync(0xffffffffu,tm0,1));
        tm0=fmaxf(tm0,__shfl_xor_sync(0xffffffffu,tm0,2));
        tm1=fmaxf(tm1,__shfl_xor_sync(0xffffffffu,tm1,1));
        tm1=fmaxf(tm1,__shfl_xor_sync(0xffffffffu,tm1,2));
        float mn0=fmaxf(m0_,tm0), mn1=fmaxf(m1_,tm1);
        float al0=__expf(m0_-mn0), al1=__expf(m1_-mn1);
        m0_=mn0; m1_=mn1;
        float s0=0.0f, s1=0.0f;
        #pragma unroll
        for(int nt=0;nt<8;nt++){
            sacc[nt][0]=__expf(sacc[nt][0]-mn0); s0+=sacc[nt][0];
            sacc[nt][1]=__expf(sacc[nt][1]-mn0); s0+=sacc[nt][1];
            sacc[nt][2]=__expf(sacc[nt][2]-mn1); s1+=sacc[nt][2];
            sacc[nt][3]=__expf(sacc[nt][3]-mn1); s1+=sacc[nt][3];
        }
        s0+=__shfl_xor_sync(0xffffffffu,s0,1); s0+=__shfl_xor_sync(0xffffffffu,s0,2);
        s1+=__shfl_xor_sync(0xffffffffu,s1,1); s1+=__shfl_xor_sync(0xffffffffu,s1,2);
        l0_=l0_*al0+s0; l1_=l1_*al1+s1;
        #pragma unroll
        for(int nt=0;nt<8;nt++){
            oacc[nt][0]*=al0; oacc[nt][1]*=al0;
            oacc[nt][2]*=al1; oacc[nt][3]*=al1;
        }
        uint32_t ph_[4][4];
        #pragma unroll
        for(int kt=0;kt<4;kt++){
            ph_[kt][0]=pack2(sacc[2*kt][0],  sacc[2*kt][1]);
            ph_[kt][1]=pack2(sacc[2*kt][2],  sacc[2*kt][3]);
            ph_[kt][2]=pack2(sacc[2*kt+1][0],sacc[2*kt+1][1]);
            ph_[kt][3]=pack2(sacc[2*kt+1][2],sacc[2*kt+1][3]);
        }
        #pragma unroll
        for(int kt=0;kt<4;kt++){
            #pragma unroll
            for(int dg=0;dg<4;dg++){
                int row=kt*16+((lane>>3)&1)*8+(lane&7);
                int ch_=dg*2+(lane>>4);
                uint32_t ad=stv+8192+row*128+((ch_^(row&7))*16);
                uint32_t vh_[4];
                LDSM4T(vh_[0],vh_[1],vh_[2],vh_[3],ad);
                #pragma unroll
                for(int p=0;p<2;p++)
                    MMA(oacc[dg*2+p],ph_[kt],vh_[p*2],vh_[p*2+1]);
            }
        }
    }
    float inv0=__fdividef(1.0f,l0_), inv1=__fdividef(1.0f,l1_);
    #pragma unroll
    for(int nt=0;nt<8;nt++){
        int dh=nt*8+j2;
        *(uint32_t*)&Ch[((size_t)(b*Ss+qi0))*Dd+h*DH+dh]=pack2(oacc[nt][0]*inv0,oacc[nt][1]*inv0);
        *(uint32_t*)&Ch[((size_t)(b*Ss+qi1))*Dd+h*DH+dh]=pack2(oacc[nt][2]*inv1,oacc[nt][3]*inv1);
    }
}

// ================= LayerNorm: fp32 in -> fp32 out + fp16 out ====================
__global__ void ln_k(const float* __restrict__ in,const float* __restrict__ g,
                     const float* __restrict__ bt,float* __restrict__ out,
                     hf* __restrict__ oh){
    const size_t row=blockIdx.x;
    const int tid=threadIdx.x, lane=tid&31, wid=tid>>5;
    __shared__ float red[4];
    float4 v=*(const float4*)&in[row*Dd+tid*4];
    float s=v.x+v.y+v.z+v.w;
    #pragma unroll
    for(int o=16;o;o>>=1)s+=__shfl_xor_sync(0xffffffffu,s,o);
    if(lane==0)red[wid]=s;
    __syncthreads();
    float mu=(red[0]+red[1]+red[2]+red[3])*(1.0f/512.0f);
    __syncthreads();
    float dx=v.x-mu,dy=v.y-mu,dz=v.z-mu,dw=v.w-mu;
    float s2=dx*dx+dy*dy+dz*dz+dw*dw;
    #pragma unroll
    for(int o=16;o;o>>=1)s2+=__shfl_xor_sync(0xffffffffu,s2,o);
    if(lane==0)red[wid]=s2;
    __syncthreads();
    float var=(red[0]+red[1]+red[2]+red[3])*(1.0f/512.0f);
    float inv=rsqrtf(var+1e-12f);
    float4 gv=*(const float4*)&g[tid*4];
    float4 bv=*(const float4*)&bt[tid*4];
    float4 o;
    o.x=dx*inv*gv.x+bv.x; o.y=dy*inv*gv.y+bv.y;
    o.z=dz*inv*gv.z+bv.z; o.w=dw*inv*gv.w+bv.w;
    *(float4*)&out[row*Dd+tid*4]=o;
    ((uint32_t*)(oh+row*Dd+tid*4))[0]=pack2(o.x,o.y);
    ((uint32_t*)(oh+row*Dd+tid*4))[1]=pack2(o.z,o.w);
}

__global__ void split_k(const float* __restrict__ s,hf* __restrict__ hi,int n4){
    int i=blockIdx.x*256+threadIdx.x;
    if(i>=n4)return;
    float4 v=((const float4*)s)[i];
    ((uint32_t*)hi)[i*2+0]=pack2(v.x,v.y);
    ((uint32_t*)hi)[i*2+1]=pack2(v.z,v.w);
}

__global__ void wprep_k(const float* __restrict__ Wq,const float* __restrict__ Wk,
                        const float* __restrict__ Wv,const float* __restrict__ Wo,
                        const float* __restrict__ Wi,const float* __restrict__ Wf,
                        hf* __restrict__ wh){
    __shared__ float t[32][33];
    int tile=blockIdx.x;
    int l=tile/3072, r=tile%3072;
    const float* src; size_t off; int K,N;
    if(r<1024){
        int m=r>>8; r&=255;
        src=(m==0?Wq:m==1?Wk:m==2?Wv:Wo)+(size_t)l*Dd*Dd;
        off=(size_t)m*Dd*Dd; K=Dd; N=Dd;
    }else if(r<2048){
        r-=1024; src=Wi+(size_t)l*Dd*Ff; off=4*Dd*Dd; K=Dd; N=Ff;
    }else{
        r-=2048; src=Wf+(size_t)l*Ff*Dd; off=4*Dd*Dd+(size_t)Dd*Ff; K=Ff; N=Dd;
    }
    hf* dh=wh+(size_t)l*LWc+off;
    int ntk=K>>5;
    int n0=(r/ntk)*32, k0=(r%ntk)*32;
    int x=threadIdx.x, y0=threadIdx.y;
    for(int j=y0;j<32;j+=8) t[j][x]=src[(size_t)(k0+j)*N+n0+x];
    __syncthreads();
    for(int j=y0;j<32;j+=8)
        dh[(size_t)(n0+j)*K+k0+x]=__float2half_rn(t[x][j]);
}

__global__ void catb_k(const float* bq,const float* bk,const float* bv,float* o,
                       const float* pb,hf* pbh){
    int i=blockIdx.x*256+threadIdx.x;
    if(i<Ll*3*Dd){
        int l=i/(3*Dd), r=i%(3*Dd);
        o[i]= r<Dd ? bq[l*Dd+r] : (r<2*Dd ? bk[l*Dd+r-Dd] : bv[l*Dd+r-2*Dd]);
    }
    int n4=(int)((size_t)Hh*Ss*Ss/4);
    for(int j=i;j<n4;j+=gridDim.x*256){
        float4 v=((const float4*)pb)[j];
        ((uint32_t*)pbh)[j*2+0]=pack2(v.x,v.y);
        ((uint32_t*)pbh)[j*2+1]=pack2(v.z,v.w);
    }
}

extern "C" void kernel_launch(void* const* d_in, const int* in_sizes, int n_in,
                              void* d_out, int out_size){
    const float* hidden=(const float*)d_in[0];
    const float* pbias=(const float*)d_in[1];
    const long long* ts=(const long long*)d_in[2];
    const float* Wq=(const float*)d_in[3];  const float* bq=(const float*)d_in[4];
    const float* Wk=(const float*)d_in[5];  const float* bk=(const float*)d_in[6];
    const float* Wv=(const float*)d_in[7];  const float* bv=(const float*)d_in[8];
    const float* Wo=(const float*)d_in[9];  const float* bo=(const float*)d_in[10];
    const float* l1g=(const float*)d_in[11];const float* l1b=(const float*)d_in[12];
    const float* Wi=(const float*)d_in[13]; const float* bi=(const float*)d_in[14];
    const float* Wf=(const float*)d_in[15]; const float* bfp=(const float*)d_in[16];
    const float* l2g=(const float*)d_in[17];const float* l2b=(const float*)d_in[18];

    float *px,*pattn,*ptmp,*pcatb;
    cudaGetSymbolAddress((void**)&px,g_x);     cudaGetSymbolAddress((void**)&pattn,g_attn);
    cudaGetSymbolAddress((void**)&ptmp,g_tmp); cudaGetSymbolAddress((void**)&pcatb,g_catb);
    hf *xh,*qkh,*ch,*ah,*fh,*wh,*pbh;
    cudaGetSymbolAddress((void**)&xh,g_xh);
    cudaGetSymbolAddress((void**)&qkh,g_qkvh);
    cudaGetSymbolAddress((void**)&ch,g_ch);
    cudaGetSymbolAddress((void**)&ah,g_ah);
    cudaGetSymbolAddress((void**)&fh,g_fh);
    cudaGetSymbolAddress((void**)&wh,g_wh);
    cudaGetSymbolAddress((void**)&pbh,g_pbh);

    cudaFuncSetAttribute(gemm_mma<0,false,2,512>, cudaFuncAttributeMaxDynamicSharedMemorySize,GSMEM);
    cudaFuncSetAttribute(gemm_mma<0,true,0,512>,  cudaFuncAttributeMaxDynamicSharedMemorySize,GSMEM);
    cudaFuncSetAttribute(gemm_mma<1,false,2,512>, cudaFuncAttributeMaxDynamicSharedMemorySize,GSMEM);
    cudaFuncSetAttribute(gemm_mma<0,true,0,2048>, cudaFuncAttributeMaxDynamicSharedMemorySize,GSMEM);
    cudaFuncSetAttribute(flash_k,cudaFuncAttributeMaxDynamicSharedMemorySize,FLSM);

    wprep_k<<<Ll*3072,dim3(32,8)>>>(Wq,Wk,Wv,Wo,Wi,Wf,wh);
    catb_k<<<512,256>>>(bq,bk,bv,pcatb,pbias,pbh);
    const int nD4=Mrows*Dd/4;
    split_k<<<(nD4+255)/256,256>>>(hidden,xh,nD4);

    const dim3 gDD(Dd/128,Mrows/128), gQKV(3*Dd/128,Mrows/128), gDF(Ff/128,Mrows/128);
    const float* X=hidden;
    for(int l=0;l<Ll;l++){
        hf* bh_=wh+(size_t)l*LWc;
        hf* wih=bh_+4*Dd*Dd;
        hf* wfh=wih+(size_t)Dd*Ff;
        float* xout=(l==Ll-1)? (float*)d_out : px;

        gemm_mma<0,false,2,512><<<gQKV,256,GSMEM>>>(xh,bh_,pcatb+l*3*Dd,nullptr,nullptr,qkh,3*Dd);
        flash_k<<<dim3(4,Bb*Hh),256,FLSM>>>(qkh,pbh,ts,ch);

        gemm_mma<0,true,0,512><<<gDD,256,GSMEM>>>(ch,bh_+3*Dd*Dd,bo+l*Dd,X,ptmp,nullptr,Dd);
        ln_k<<<Mrows,128>>>(ptmp,l1g+l*Dd,l1b+l*Dd,pattn,ah);

        gemm_mma<1,false,2,512><<<gDF,256,GSMEM>>>(ah,wih,bi+l*Ff,nullptr,nullptr,fh,Ff);
        gemm_mma<0,true,0,2048><<<gDD,256,GSMEM>>>(fh,wfh,bfp+l*Dd,pattn,ptmp,nullptr,Dd);
        ln_k<<<Mrows,128>>>(ptmp,l2g+l*Dd,l2b+l*Dd,xout,xh);
        X=xout;
    }
}